// round 1
// baseline (speedup 1.0000x reference)
#include <cuda_runtime.h>
#include <math.h>

// ---------------------------------------------------------------------------
// att_lstm: fused multimodal projection -> LayerNorm-LSTM -> attention -> head
// Round 0: full fp32 SIMT implementation. Tiled SGEMM (128x128x8, 8x8/thread),
// algebraic rewrite of the V einsum (ctx = wv_W @ (attn-weighted lstm_out)).
// ---------------------------------------------------------------------------

#define B_    2048
#define SEQ_  16
#define DIM_  1024
#define HID_  512
#define DK_   512
#define NH_   4
#define DH_   128
#define G4_   (4 * HID_)      // 2048
#define BS_   (B_ * SEQ_)     // 32768
#define EPS_  1e-5f

// ------------------------------- scratch -----------------------------------
__device__ float d_vt  [BS_ * DIM_];        // fused+relu projection   (B,S,1024)
__device__ float d_gx  [BS_ * G4_];         // LN(x@W_ih^T)            (B,S,2048)
__device__ float d_hw  [B_  * G4_];         // h@W_hh^T per step       (B,2048)
__device__ float d_h   [B_  * HID_];
__device__ float d_c   [B_  * HID_];
__device__ float d_lstm[BS_ * HID_];        // all h_t                 (B,S,512)
__device__ float d_kall[BS_ * DK_];         // k projection            (B,S,512)
__device__ float d_qb  [B_  * DK_];
__device__ float d_m   [B_  * NH_ * HID_];  // attn-weighted lstm_out  (B,4,512)
__device__ float d_ctx [B_  * NH_ * DK_];   // (B,2048)
__device__ float d_oh  [B_  * DK_];
__device__ float d_diff[B_];

// --------------------------- helpers ---------------------------------------
__device__ __forceinline__ float sigm(float x) { return 1.0f / (1.0f + expf(-x)); }

__device__ __forceinline__ float2 blockReduce2(float a, float b) {
    __shared__ float s1[8], s2[8];
    const unsigned m = 0xffffffffu;
    #pragma unroll
    for (int o = 16; o > 0; o >>= 1) {
        a += __shfl_down_sync(m, a, o);
        b += __shfl_down_sync(m, b, o);
    }
    int w = threadIdx.x >> 5, l = threadIdx.x & 31;
    if (l == 0) { s1[w] = a; s2[w] = b; }
    __syncthreads();
    int nw = blockDim.x >> 5;
    if (w == 0) {
        a = (l < nw) ? s1[l] : 0.0f;
        b = (l < nw) ? s2[l] : 0.0f;
        #pragma unroll
        for (int o = 4; o > 0; o >>= 1) {
            a += __shfl_down_sync(m, a, o);
            b += __shfl_down_sync(m, b, o);
        }
        if (l == 0) { s1[0] = a; s2[0] = b; }
    }
    __syncthreads();
    float2 r = make_float2(s1[0], s2[0]);
    __syncthreads();
    return r;
}

// --------------------------- generic SGEMM ----------------------------------
// C[m,n] = sum_k A[m,k]*B[n,k] (+bias[n]) ; A (M,K) ld=lda, B (N,K) ld=ldb.
// Batched over gridDim.z via element strides. 256 threads, 128x128 tile, BK=8.
__global__ void __launch_bounds__(256)
sgemm_bt(const float* __restrict__ A, int lda, long sAz,
         const float* __restrict__ Bm, int ldb, long sBz,
         float* __restrict__ C, int ldc, long sCz,
         int K,
         const float* __restrict__ bias, int sbz, int act)
{
    __shared__ float As[8][128];
    __shared__ float Bs[8][128];
    const int tid = threadIdx.x;
    const int m0 = blockIdx.y * 128, n0 = blockIdx.x * 128;
    A  += (long)blockIdx.z * sAz;
    Bm += (long)blockIdx.z * sBz;
    C  += (long)blockIdx.z * sCz;
    const float* bz = bias ? bias + (long)blockIdx.z * sbz : (const float*)0;

    const int tx = tid & 15, ty = tid >> 4;
    const int lr = tid >> 1, lc = (tid & 1) * 4;

    float acc[8][8];
    #pragma unroll
    for (int i = 0; i < 8; i++)
        #pragma unroll
        for (int j = 0; j < 8; j++) acc[i][j] = 0.0f;

    const float* Aptr = A  + (long)(m0 + lr) * lda + lc;
    const float* Bptr = Bm + (long)(n0 + lr) * ldb + lc;

    for (int k0 = 0; k0 < K; k0 += 8) {
        float4 a4 = *(const float4*)(Aptr + k0);
        float4 b4 = *(const float4*)(Bptr + k0);
        As[lc + 0][lr] = a4.x; As[lc + 1][lr] = a4.y;
        As[lc + 2][lr] = a4.z; As[lc + 3][lr] = a4.w;
        Bs[lc + 0][lr] = b4.x; Bs[lc + 1][lr] = b4.y;
        Bs[lc + 2][lr] = b4.z; Bs[lc + 3][lr] = b4.w;
        __syncthreads();
        #pragma unroll
        for (int kk = 0; kk < 8; kk++) {
            float ar[8], br[8];
            #pragma unroll
            for (int i = 0; i < 8; i++) ar[i] = As[kk][ty * 8 + i];
            #pragma unroll
            for (int j = 0; j < 8; j++) br[j] = Bs[kk][tx * 8 + j];
            #pragma unroll
            for (int i = 0; i < 8; i++)
                #pragma unroll
                for (int j = 0; j < 8; j++) acc[i][j] += ar[i] * br[j];
        }
        __syncthreads();
    }

    #pragma unroll
    for (int i = 0; i < 8; i++) {
        int mm = m0 + ty * 8 + i;
        #pragma unroll
        for (int j = 0; j < 8; j += 4) {
            int nn = n0 + tx * 8 + j;
            float4 v;
            v.x = acc[i][j];     v.y = acc[i][j + 1];
            v.z = acc[i][j + 2]; v.w = acc[i][j + 3];
            if (bz) { v.x += bz[nn]; v.y += bz[nn + 1]; v.z += bz[nn + 2]; v.w += bz[nn + 3]; }
            if (act) {
                v.x = fmaxf(v.x, 0.0f); v.y = fmaxf(v.y, 0.0f);
                v.z = fmaxf(v.z, 0.0f); v.w = fmaxf(v.w, 0.0f);
            }
            *(float4*)(C + (long)mm * ldc + nn) = v;
        }
    }
}

// Fusion GEMM: A is the virtual concat [visual|text|user|cat] along K (4096).
// C[r,n] = relu( sum_k mods[r,k]*fus_W[n,k] + fus_b[n] ), N=1024.
__global__ void __launch_bounds__(256)
sgemm_concat4(const float* __restrict__ p0, const float* __restrict__ p1,
              const float* __restrict__ p2, const float* __restrict__ p3,
              const float* __restrict__ Bm,   // fus_W (1024, 4096)
              float* __restrict__ C,          // d_vt (BS, 1024)
              const float* __restrict__ bias) // fus_b
{
    __shared__ float As[8][128];
    __shared__ float Bs[8][128];
    const int tid = threadIdx.x;
    const int m0 = blockIdx.y * 128, n0 = blockIdx.x * 128;
    const int tx = tid & 15, ty = tid >> 4;
    const int lr = tid >> 1, lc = (tid & 1) * 4;

    float acc[8][8];
    #pragma unroll
    for (int i = 0; i < 8; i++)
        #pragma unroll
        for (int j = 0; j < 8; j++) acc[i][j] = 0.0f;

    for (int k0 = 0; k0 < 4096; k0 += 8) {
        int seg = k0 >> 10;
        const float* Ap = (seg == 0) ? p0 : (seg == 1) ? p1 : (seg == 2) ? p2 : p3;
        int klocal = (k0 & 1023) + lc;
        float4 a4 = *(const float4*)(Ap + (long)(m0 + lr) * DIM_ + klocal);
        float4 b4 = *(const float4*)(Bm + (long)(n0 + lr) * 4096 + k0 + lc);
        As[lc + 0][lr] = a4.x; As[lc + 1][lr] = a4.y;
        As[lc + 2][lr] = a4.z; As[lc + 3][lr] = a4.w;
        Bs[lc + 0][lr] = b4.x; Bs[lc + 1][lr] = b4.y;
        Bs[lc + 2][lr] = b4.z; Bs[lc + 3][lr] = b4.w;
        __syncthreads();
        #pragma unroll
        for (int kk = 0; kk < 8; kk++) {
            float ar[8], br[8];
            #pragma unroll
            for (int i = 0; i < 8; i++) ar[i] = As[kk][ty * 8 + i];
            #pragma unroll
            for (int j = 0; j < 8; j++) br[j] = Bs[kk][tx * 8 + j];
            #pragma unroll
            for (int i = 0; i < 8; i++)
                #pragma unroll
                for (int j = 0; j < 8; j++) acc[i][j] += ar[i] * br[j];
        }
        __syncthreads();
    }

    #pragma unroll
    for (int i = 0; i < 8; i++) {
        int mm = m0 + ty * 8 + i;
        #pragma unroll
        for (int j = 0; j < 8; j += 4) {
            int nn = n0 + tx * 8 + j;
            float4 v;
            v.x = fmaxf(acc[i][j]     + bias[nn],     0.0f);
            v.y = fmaxf(acc[i][j + 1] + bias[nn + 1], 0.0f);
            v.z = fmaxf(acc[i][j + 2] + bias[nn + 2], 0.0f);
            v.w = fmaxf(acc[i][j + 3] + bias[nn + 3], 0.0f);
            *(float4*)(C + (long)mm * DIM_ + nn) = v;
        }
    }
}

// In-place LayerNorm over rows of length 2048 (gates_x = LN(x@W_ih^T)).
__global__ void __launch_bounds__(256)
ln_rows_kernel(float* __restrict__ x, const float* __restrict__ g,
               const float* __restrict__ b)
{
    __shared__ float sx[G4_];
    long base = (long)blockIdx.x * G4_;
    float s = 0.0f, ss = 0.0f;
    for (int j = threadIdx.x; j < G4_; j += 256) {
        float v = x[base + j];
        sx[j] = v; s += v; ss += v * v;
    }
    float2 r = blockReduce2(s, ss);
    float mean = r.x * (1.0f / G4_);
    float var  = r.y * (1.0f / G4_) - mean * mean;
    float inv  = rsqrtf(var + EPS_);
    for (int j = threadIdx.x; j < G4_; j += 256)
        x[base + j] = (sx[j] - mean) * inv * g[j] + b[j];
}

// One LSTM step: LN the hh-gates, combine with precomputed gates_x, update c/h.
__global__ void __launch_bounds__(256)
lstm_cell_kernel(const float* __restrict__ hw,       // (B,2048) raw h@W_hh^T
                 const float* __restrict__ gx,       // (B*S,2048) LN'd x-gates
                 const float* __restrict__ g_hh, const float* __restrict__ b_hh,
                 const float* __restrict__ g_c,  const float* __restrict__ b_c,
                 float* __restrict__ h, float* __restrict__ c,
                 float* __restrict__ lstm, int t)
{
    __shared__ float sg[G4_];
    const int b = blockIdx.x;
    const int tid = threadIdx.x;
    const float* row = hw + (long)b * G4_;
    float s = 0.0f, ss = 0.0f;
    for (int j = tid; j < G4_; j += 256) {
        float v = row[j];
        sg[j] = v; s += v; ss += v * v;
    }
    float2 r = blockReduce2(s, ss);
    float mean = r.x * (1.0f / G4_);
    float var  = r.y * (1.0f / G4_) - mean * mean;
    float inv  = rsqrtf(var + EPS_);

    const float* gxr = gx + ((long)b * SEQ_ + t) * G4_;
    float cval[2];
    float sc = 0.0f, ssc = 0.0f;
    #pragma unroll
    for (int rr = 0; rr < 2; rr++) {
        int j = rr * 256 + tid;
        float gi = (sg[j]        - mean) * inv * g_hh[j]        + b_hh[j]        + gxr[j];
        float gf = (sg[512 + j]  - mean) * inv * g_hh[512 + j]  + b_hh[512 + j]  + gxr[512 + j];
        float gg = (sg[1024 + j] - mean) * inv * g_hh[1024 + j] + b_hh[1024 + j] + gxr[1024 + j];
        float cn = sigm(gf) * c[(long)b * HID_ + j] + sigm(gi) * tanhf(gg);
        cval[rr] = cn;
        c[(long)b * HID_ + j] = cn;
        sc += cn; ssc += cn * cn;
    }
    float2 rc = blockReduce2(sc, ssc);
    float meanc = rc.x * (1.0f / HID_);
    float varc  = rc.y * (1.0f / HID_) - meanc * meanc;
    float invc  = rsqrtf(varc + EPS_);
    #pragma unroll
    for (int rr = 0; rr < 2; rr++) {
        int j = rr * 256 + tid;
        float go = (sg[1536 + j] - mean) * inv * g_hh[1536 + j] + b_hh[1536 + j] + gxr[1536 + j];
        float hn = sigm(go) * tanhf((cval[rr] - meanc) * invc * g_c[j] + b_c[j]);
        h[(long)b * HID_ + j] = hn;
        lstm[((long)b * SEQ_ + t) * HID_ + j] = hn;
    }
}

// Per (b,h): scores -> softmax -> m[b,h,:] = sum_s attn_s * lstm_out[b,s,:]
__global__ void __launch_bounds__(128)
attn_kernel(const float* __restrict__ kall, const float* __restrict__ qb,
            const float* __restrict__ lstm, float* __restrict__ mbuf)
{
    const int hidx = blockIdx.x;     // head
    const int b    = blockIdx.y;     // batch
    const int tid  = threadIdx.x;    // 128 = DH
    __shared__ float ssc[SEQ_];
    __shared__ float wsum[SEQ_][4];

    float qv = qb[(long)b * DK_ + hidx * DH_ + tid];
    int w = tid >> 5, l = tid & 31;
    for (int s = 0; s < SEQ_; s++) {
        float v = kall[((long)b * SEQ_ + s) * DK_ + hidx * DH_ + tid] * qv;
        #pragma unroll
        for (int o = 16; o > 0; o >>= 1) v += __shfl_down_sync(0xffffffffu, v, o);
        if (l == 0) wsum[s][w] = v;
    }
    __syncthreads();
    if (tid < SEQ_) {
        float sc = wsum[tid][0] + wsum[tid][1] + wsum[tid][2] + wsum[tid][3];
        ssc[tid] = sc * 0.08838834764831845f;  // 1/sqrt(128)
    }
    __syncthreads();

    float e[SEQ_];
    float mx = -1e30f;
    #pragma unroll
    for (int s = 0; s < SEQ_; s++) mx = fmaxf(mx, ssc[s]);
    float den = 0.0f;
    #pragma unroll
    for (int s = 0; s < SEQ_; s++) { e[s] = expf(ssc[s] - mx); den += e[s]; }
    float dinv = 1.0f / den;

    #pragma unroll
    for (int rr = 0; rr < HID_ / 128; rr++) {
        int d = rr * 128 + tid;
        float acc = 0.0f;
        #pragma unroll
        for (int s = 0; s < SEQ_; s++)
            acc += e[s] * lstm[((long)b * SEQ_ + s) * HID_ + d];
        mbuf[((long)b * NH_ + hidx) * HID_ + d] = acc * dinv;
    }
}

// output[b] = out_h[b,:] . out_W + out_b ; diff[b] = (output - label[b,15,0])^2
__global__ void __launch_bounds__(256)
out_final_kernel(const float* __restrict__ oh, const float* __restrict__ outW,
                 const float* __restrict__ outb, const float* __restrict__ label,
                 float* __restrict__ out, float* __restrict__ diff)
{
    int w = threadIdx.x >> 5, l = threadIdx.x & 31;
    int b = blockIdx.x * 8 + w;
    float s = 0.0f;
    for (int j = l; j < DK_; j += 32) s += oh[(long)b * DK_ + j] * outW[j];
    #pragma unroll
    for (int o = 16; o > 0; o >>= 1) s += __shfl_down_sync(0xffffffffu, s, o);
    if (l == 0) {
        float v = s + outb[0];
        out[1 + b] = v;
        float d = v - label[(long)b * SEQ_ + (SEQ_ - 1)];
        diff[b] = d * d;
    }
}

__global__ void __launch_bounds__(256)
loss_kernel(const float* __restrict__ diff, float* __restrict__ out)
{
    float s = 0.0f;
    for (int j = threadIdx.x; j < B_; j += 256) s += diff[j];
    float2 r = blockReduce2(s, 0.0f);
    if (threadIdx.x == 0) out[0] = r.x * (1.0f / B_);
}

// ------------------------------- launch -------------------------------------
extern "C" void kernel_launch(void* const* d_in, const int* in_sizes, int n_in,
                              void* d_out, int out_size)
{
    const float* visual = (const float*)d_in[0];
    const float* text   = (const float*)d_in[1];
    const float* user   = (const float*)d_in[2];
    const float* cat    = (const float*)d_in[3];
    const float* label  = (const float*)d_in[4];
    const float* h0     = (const float*)d_in[5];
    const float* c0     = (const float*)d_in[6];
    const float* fus_W  = (const float*)d_in[7];
    const float* fus_b  = (const float*)d_in[8];
    const float* W_ih   = (const float*)d_in[9];
    const float* W_hh   = (const float*)d_in[10];
    const float* g_ih   = (const float*)d_in[11];
    const float* b_ih   = (const float*)d_in[12];
    const float* g_hh   = (const float*)d_in[13];
    const float* b_hh   = (const float*)d_in[14];
    const float* g_c    = (const float*)d_in[15];
    const float* b_c    = (const float*)d_in[16];
    const float* wq_W   = (const float*)d_in[17];
    const float* wq_b   = (const float*)d_in[18];
    const float* wk_W   = (const float*)d_in[19];
    const float* wk_b   = (const float*)d_in[20];
    const float* wv_W   = (const float*)d_in[21];
    const float* wv_b   = (const float*)d_in[22];
    const float* wout_W = (const float*)d_in[23];
    const float* wout_b = (const float*)d_in[24];
    const float* out_W  = (const float*)d_in[25];
    const float* out_b  = (const float*)d_in[26];
    float* out = (float*)d_out;

    float *vt, *gx, *hw, *h, *c, *lstm, *kall, *qb, *m, *ctx, *oh, *diff;
    cudaGetSymbolAddress((void**)&vt,   d_vt);
    cudaGetSymbolAddress((void**)&gx,   d_gx);
    cudaGetSymbolAddress((void**)&hw,   d_hw);
    cudaGetSymbolAddress((void**)&h,    d_h);
    cudaGetSymbolAddress((void**)&c,    d_c);
    cudaGetSymbolAddress((void**)&lstm, d_lstm);
    cudaGetSymbolAddress((void**)&kall, d_kall);
    cudaGetSymbolAddress((void**)&qb,   d_qb);
    cudaGetSymbolAddress((void**)&m,    d_m);
    cudaGetSymbolAddress((void**)&ctx,  d_ctx);
    cudaGetSymbolAddress((void**)&oh,   d_oh);
    cudaGetSymbolAddress((void**)&diff, d_diff);

    // 1. fused multimodal projection + relu: v_t (32768, 1024)
    sgemm_concat4<<<dim3(DIM_ / 128, BS_ / 128), 256>>>(
        visual, text, user, cat, fus_W, vt, fus_b);

    // 2. all-timestep input gates: gx = v_t @ W_ih^T (32768, 2048), then LN
    sgemm_bt<<<dim3(G4_ / 128, BS_ / 128), 256>>>(
        vt, DIM_, 0, W_ih, DIM_, 0, gx, G4_, 0, DIM_, (const float*)0, 0, 0);
    ln_rows_kernel<<<BS_, 256>>>(gx, g_ih, b_ih);

    // 3. LSTM recurrence
    cudaMemcpyAsync(h, h0, (size_t)B_ * HID_ * sizeof(float), cudaMemcpyDeviceToDevice, 0);
    cudaMemcpyAsync(c, c0, (size_t)B_ * HID_ * sizeof(float), cudaMemcpyDeviceToDevice, 0);
    for (int t = 0; t < SEQ_; t++) {
        sgemm_bt<<<dim3(G4_ / 128, B_ / 128), 256>>>(
            h, HID_, 0, W_hh, HID_, 0, hw, G4_, 0, HID_, (const float*)0, 0, 0);
        lstm_cell_kernel<<<B_, 256>>>(hw, gx, g_hh, b_hh, g_c, b_c, h, c, lstm, t);
    }

    // 4. k / q projections
    sgemm_bt<<<dim3(DK_ / 128, BS_ / 128), 256>>>(
        lstm, HID_, 0, wk_W, HID_, 0, kall, DK_, 0, HID_, wk_b, 0, 0);
    sgemm_bt<<<dim3(DK_ / 128, B_ / 128), 256>>>(
        h, HID_, 0, wq_W, HID_, 0, qb, DK_, 0, HID_, wq_b, 0, 0);

    // 5. attention scores+softmax+weighted lstm_out -> m (B,4,512)
    attn_kernel<<<dim3(NH_, B_), 128>>>(kall, qb, lstm, m);

    // 6. ctx[b, h*512+k] = wv_W[h] . m[b,h] + wv_b[h]   (batched over z=head)
    sgemm_bt<<<dim3(DK_ / 128, B_ / 128, NH_), 256>>>(
        m, NH_ * HID_, HID_, wv_W, HID_, (long)DK_ * HID_,
        ctx, NH_ * DK_, DK_, HID_, wv_b, DK_, 0);

    // 7. out_h = ctx @ wout_W^T + wout_b  (2048 x 512 x 2048)
    sgemm_bt<<<dim3(DK_ / 128, B_ / 128), 256>>>(
        ctx, NH_ * DK_, 0, wout_W, NH_ * DK_, 0, oh, DK_, 0, NH_ * DK_, wout_b, 0, 0);

    // 8. final projection + squared error, then loss reduction
    out_final_kernel<<<B_ / 8, 256>>>(oh, out_W, out_b, label, out, diff);
    loss_kernel<<<1, 256>>>(diff, out);
}

// round 2
// speedup vs baseline: 2.8282x; 2.8282x over previous
#include <cuda_runtime.h>
#include <math.h>

// ---------------------------------------------------------------------------
// att_lstm round 2: all GEMMs on tensor cores via mma.sync tf32 (m16n8k8),
// cp.async double-buffered 128x128x16 tiles, cvt.rna rounding.
// ---------------------------------------------------------------------------

#define B_    2048
#define SEQ_  16
#define DIM_  1024
#define HID_  512
#define DK_   512
#define NH_   4
#define DH_   128
#define G4_   (4 * HID_)      // 2048
#define BS_   (B_ * SEQ_)     // 32768
#define EPS_  1e-5f

#define BM 128
#define BN 128
#define BK 16
#define LDT 20                // padded smem row stride (floats)

// ------------------------------- scratch -----------------------------------
__device__ float d_vt  [BS_ * DIM_];
__device__ float d_gx  [BS_ * G4_];
__device__ float d_hw  [B_  * G4_];
__device__ float d_h   [B_  * HID_];
__device__ float d_c   [B_  * HID_];
__device__ float d_lstm[BS_ * HID_];
__device__ float d_kall[BS_ * DK_];
__device__ float d_qb  [B_  * DK_];
__device__ float d_m   [B_  * NH_ * HID_];
__device__ float d_ctx [B_  * NH_ * DK_];
__device__ float d_oh  [B_  * DK_];
__device__ float d_diff[B_];

// --------------------------- helpers ---------------------------------------
__device__ __forceinline__ float sigm(float x) { return 1.0f / (1.0f + expf(-x)); }

__device__ __forceinline__ unsigned f2tf(float f) {
    unsigned u;
    asm("cvt.rna.tf32.f32 %0, %1;" : "=r"(u) : "f"(f));
    return u;
}

__device__ __forceinline__ void mma_tf32(float* c,
    unsigned a0, unsigned a1, unsigned a2, unsigned a3,
    unsigned b0, unsigned b1)
{
    asm volatile(
        "mma.sync.aligned.m16n8k8.row.col.f32.tf32.tf32.f32 "
        "{%0,%1,%2,%3},{%4,%5,%6,%7},{%8,%9},{%0,%1,%2,%3};\n"
        : "+f"(c[0]), "+f"(c[1]), "+f"(c[2]), "+f"(c[3])
        : "r"(a0), "r"(a1), "r"(a2), "r"(a3), "r"(b0), "r"(b1));
}

__device__ __forceinline__ void cpa16(unsigned dst, const void* src) {
    asm volatile("cp.async.cg.shared.global [%0], [%1], 16;\n" :: "r"(dst), "l"(src));
}
__device__ __forceinline__ void cpa_commit() { asm volatile("cp.async.commit_group;\n"); }
__device__ __forceinline__ void cpa_wait1()  { asm volatile("cp.async.wait_group 1;\n"); }

__device__ __forceinline__ float2 blockReduce2(float a, float b) {
    __shared__ float s1[8], s2[8];
    const unsigned m = 0xffffffffu;
    #pragma unroll
    for (int o = 16; o > 0; o >>= 1) {
        a += __shfl_down_sync(m, a, o);
        b += __shfl_down_sync(m, b, o);
    }
    int w = threadIdx.x >> 5, l = threadIdx.x & 31;
    if (l == 0) { s1[w] = a; s2[w] = b; }
    __syncthreads();
    int nw = blockDim.x >> 5;
    if (w == 0) {
        a = (l < nw) ? s1[l] : 0.0f;
        b = (l < nw) ? s2[l] : 0.0f;
        #pragma unroll
        for (int o = 4; o > 0; o >>= 1) {
            a += __shfl_down_sync(m, a, o);
            b += __shfl_down_sync(m, b, o);
        }
        if (l == 0) { s1[0] = a; s2[0] = b; }
    }
    __syncthreads();
    float2 r = make_float2(s1[0], s2[0]);
    __syncthreads();
    return r;
}

// --------------------------- tf32 tensor-core GEMM --------------------------
// C[m,n] = sum_k A[m,k]*B[n,k] (+bias[n]) (+relu) ; z-batched via strides.
// 256 threads = 8 warps (4 m x 2 n), warp tile 32x64, mma m16n8k8 tf32.
__global__ void __launch_bounds__(256)
tgemm_bt(const float* __restrict__ A, int lda, long sAz,
         const float* __restrict__ Bm, int ldb, long sBz,
         float* __restrict__ C, int ldc, long sCz,
         int K,
         const float* __restrict__ bias, int sbz, int act)
{
    __shared__ __align__(16) float As[2][BM * LDT];
    __shared__ __align__(16) float Bs[2][BN * LDT];
    const int tid = threadIdx.x;
    const int m0 = blockIdx.y * BM, n0 = blockIdx.x * BN;
    A  += (long)blockIdx.z * sAz;
    Bm += (long)blockIdx.z * sBz;
    C  += (long)blockIdx.z * sCz;
    const float* bz = bias ? bias + (long)blockIdx.z * sbz : (const float*)0;

    const int w = tid >> 5, lane = tid & 31;
    const int wm = w & 3, wn = w >> 1 & 0 ? 0 : (w >> 2);   // wn = w>>2
    const int gid = lane >> 2, tig = lane & 3;

    const unsigned sA0 = (unsigned)__cvta_generic_to_shared(&As[0][0]);
    const unsigned sB0 = (unsigned)__cvta_generic_to_shared(&Bs[0][0]);

    const int lrow = tid >> 2;          // 0..63
    const int lc4  = (tid & 3) * 4;     // 0,4,8,12

    float acc[2][8][4];
    #pragma unroll
    for (int i = 0; i < 2; i++)
        #pragma unroll
        for (int j = 0; j < 8; j++)
            #pragma unroll
            for (int q = 0; q < 4; q++) acc[i][j][q] = 0.0f;

    const int KT = K / BK;

    // prolog: stage 0
    #pragma unroll
    for (int b = 0; b < 2; b++) {
        int r = lrow + b * 64;
        cpa16(sA0 + (unsigned)((r * LDT + lc4) * 4), A  + (long)(m0 + r) * lda + lc4);
        cpa16(sB0 + (unsigned)((r * LDT + lc4) * 4), Bm + (long)(n0 + r) * ldb + lc4);
    }
    cpa_commit();

    for (int t = 0; t < KT; t++) {
        if (t + 1 < KT) {
            int k0 = (t + 1) * BK, s = (t + 1) & 1;
            #pragma unroll
            for (int b = 0; b < 2; b++) {
                int r = lrow + b * 64;
                cpa16(sA0 + (unsigned)((s * BM * LDT + r * LDT + lc4) * 4),
                      A  + (long)(m0 + r) * lda + k0 + lc4);
                cpa16(sB0 + (unsigned)((s * BN * LDT + r * LDT + lc4) * 4),
                      Bm + (long)(n0 + r) * ldb + k0 + lc4);
            }
        }
        cpa_commit();
        cpa_wait1();
        __syncthreads();

        const float* as = As[t & 1];
        const float* bs = Bs[t & 1];
        #pragma unroll
        for (int kk = 0; kk < 2; kk++) {
            const int k = kk * 8 + tig;
            unsigned af[2][4], bf[8][2];
            #pragma unroll
            for (int i = 0; i < 2; i++) {
                int r0 = wm * 32 + i * 16 + gid;
                af[i][0] = f2tf(as[r0 * LDT + k]);
                af[i][1] = f2tf(as[(r0 + 8) * LDT + k]);
                af[i][2] = f2tf(as[r0 * LDT + k + 4]);
                af[i][3] = f2tf(as[(r0 + 8) * LDT + k + 4]);
            }
            #pragma unroll
            for (int j = 0; j < 8; j++) {
                int n = wn * 64 + j * 8 + gid;
                bf[j][0] = f2tf(bs[n * LDT + k]);
                bf[j][1] = f2tf(bs[n * LDT + k + 4]);
            }
            #pragma unroll
            for (int i = 0; i < 2; i++)
                #pragma unroll
                for (int j = 0; j < 8; j++)
                    mma_tf32(acc[i][j], af[i][0], af[i][1], af[i][2], af[i][3],
                             bf[j][0], bf[j][1]);
        }
        __syncthreads();
    }

    // epilogue
    #pragma unroll
    for (int i = 0; i < 2; i++) {
        int r0 = m0 + wm * 32 + i * 16 + gid;
        #pragma unroll
        for (int j = 0; j < 8; j++) {
            int col = n0 + wn * 64 + j * 8 + 2 * tig;
            float bx = 0.0f, by = 0.0f;
            if (bz) { bx = bz[col]; by = bz[col + 1]; }
            float2 v0 = make_float2(acc[i][j][0] + bx, acc[i][j][1] + by);
            float2 v1 = make_float2(acc[i][j][2] + bx, acc[i][j][3] + by);
            if (act) {
                v0.x = fmaxf(v0.x, 0.0f); v0.y = fmaxf(v0.y, 0.0f);
                v1.x = fmaxf(v1.x, 0.0f); v1.y = fmaxf(v1.y, 0.0f);
            }
            *(float2*)(C + (long)r0 * ldc + col) = v0;
            *(float2*)(C + (long)(r0 + 8) * ldc + col) = v1;
        }
    }
}

// Fusion GEMM over virtual concat [visual|text|user|cat] (K=4096), relu+bias.
__global__ void __launch_bounds__(256)
tgemm_concat4(const float* __restrict__ p0, const float* __restrict__ p1,
              const float* __restrict__ p2, const float* __restrict__ p3,
              const float* __restrict__ Bm,   // fus_W (1024, 4096)
              float* __restrict__ C,          // d_vt (BS, 1024)
              const float* __restrict__ bias)
{
    __shared__ __align__(16) float As[2][BM * LDT];
    __shared__ __align__(16) float Bs[2][BN * LDT];
    const int tid = threadIdx.x;
    const int m0 = blockIdx.y * BM, n0 = blockIdx.x * BN;
    const int w = tid >> 5, lane = tid & 31;
    const int wm = w & 3, wn = w >> 2;
    const int gid = lane >> 2, tig = lane & 3;

    const unsigned sA0 = (unsigned)__cvta_generic_to_shared(&As[0][0]);
    const unsigned sB0 = (unsigned)__cvta_generic_to_shared(&Bs[0][0]);
    const int lrow = tid >> 2;
    const int lc4  = (tid & 3) * 4;

    float acc[2][8][4];
    #pragma unroll
    for (int i = 0; i < 2; i++)
        #pragma unroll
        for (int j = 0; j < 8; j++)
            #pragma unroll
            for (int q = 0; q < 4; q++) acc[i][j][q] = 0.0f;

    const int KT = 4096 / BK;   // 256

    // prolog
    #pragma unroll
    for (int b = 0; b < 2; b++) {
        int r = lrow + b * 64;
        cpa16(sA0 + (unsigned)((r * LDT + lc4) * 4), p0 + (long)(m0 + r) * DIM_ + lc4);
        cpa16(sB0 + (unsigned)((r * LDT + lc4) * 4), Bm + (long)(n0 + r) * 4096 + lc4);
    }
    cpa_commit();

    for (int t = 0; t < KT; t++) {
        if (t + 1 < KT) {
            int k0 = (t + 1) * BK, s = (t + 1) & 1;
            int seg = k0 >> 10;
            const float* Ap = (seg == 0) ? p0 : (seg == 1) ? p1 : (seg == 2) ? p2 : p3;
            int kl = k0 & 1023;
            #pragma unroll
            for (int b = 0; b < 2; b++) {
                int r = lrow + b * 64;
                cpa16(sA0 + (unsigned)((s * BM * LDT + r * LDT + lc4) * 4),
                      Ap + (long)(m0 + r) * DIM_ + kl + lc4);
                cpa16(sB0 + (unsigned)((s * BN * LDT + r * LDT + lc4) * 4),
                      Bm + (long)(n0 + r) * 4096 + k0 + lc4);
            }
        }
        cpa_commit();
        cpa_wait1();
        __syncthreads();

        const float* as = As[t & 1];
        const float* bs = Bs[t & 1];
        #pragma unroll
        for (int kk = 0; kk < 2; kk++) {
            const int k = kk * 8 + tig;
            unsigned af[2][4], bf[8][2];
            #pragma unroll
            for (int i = 0; i < 2; i++) {
                int r0 = wm * 32 + i * 16 + gid;
                af[i][0] = f2tf(as[r0 * LDT + k]);
                af[i][1] = f2tf(as[(r0 + 8) * LDT + k]);
                af[i][2] = f2tf(as[r0 * LDT + k + 4]);
                af[i][3] = f2tf(as[(r0 + 8) * LDT + k + 4]);
            }
            #pragma unroll
            for (int j = 0; j < 8; j++) {
                int n = wn * 64 + j * 8 + gid;
                bf[j][0] = f2tf(bs[n * LDT + k]);
                bf[j][1] = f2tf(bs[n * LDT + k + 4]);
            }
            #pragma unroll
            for (int i = 0; i < 2; i++)
                #pragma unroll
                for (int j = 0; j < 8; j++)
                    mma_tf32(acc[i][j], af[i][0], af[i][1], af[i][2], af[i][3],
                             bf[j][0], bf[j][1]);
        }
        __syncthreads();
    }

    #pragma unroll
    for (int i = 0; i < 2; i++) {
        int r0 = m0 + wm * 32 + i * 16 + gid;
        #pragma unroll
        for (int j = 0; j < 8; j++) {
            int col = n0 + wn * 64 + j * 8 + 2 * tig;
            float bx = bias[col], by = bias[col + 1];
            float2 v0 = make_float2(fmaxf(acc[i][j][0] + bx, 0.0f),
                                    fmaxf(acc[i][j][1] + by, 0.0f));
            float2 v1 = make_float2(fmaxf(acc[i][j][2] + bx, 0.0f),
                                    fmaxf(acc[i][j][3] + by, 0.0f));
            *(float2*)(C + (long)r0 * DIM_ + col) = v0;
            *(float2*)(C + (long)(r0 + 8) * DIM_ + col) = v1;
        }
    }
}

// In-place LayerNorm over rows of length 2048.
__global__ void __launch_bounds__(256)
ln_rows_kernel(float* __restrict__ x, const float* __restrict__ g,
               const float* __restrict__ b)
{
    __shared__ float sx[G4_];
    long base = (long)blockIdx.x * G4_;
    float s = 0.0f, ss = 0.0f;
    for (int j = threadIdx.x; j < G4_; j += 256) {
        float v = x[base + j];
        sx[j] = v; s += v; ss += v * v;
    }
    float2 r = blockReduce2(s, ss);
    float mean = r.x * (1.0f / G4_);
    float var  = r.y * (1.0f / G4_) - mean * mean;
    float inv  = rsqrtf(var + EPS_);
    for (int j = threadIdx.x; j < G4_; j += 256)
        x[base + j] = (sx[j] - mean) * inv * g[j] + b[j];
}

// One LSTM step.
__global__ void __launch_bounds__(256)
lstm_cell_kernel(const float* __restrict__ hw,
                 const float* __restrict__ gx,
                 const float* __restrict__ g_hh, const float* __restrict__ b_hh,
                 const float* __restrict__ g_c,  const float* __restrict__ b_c,
                 float* __restrict__ h, float* __restrict__ c,
                 float* __restrict__ lstm, int t)
{
    __shared__ float sg[G4_];
    const int b = blockIdx.x;
    const int tid = threadIdx.x;
    const float* row = hw + (long)b * G4_;
    float s = 0.0f, ss = 0.0f;
    for (int j = tid; j < G4_; j += 256) {
        float v = row[j];
        sg[j] = v; s += v; ss += v * v;
    }
    float2 r = blockReduce2(s, ss);
    float mean = r.x * (1.0f / G4_);
    float var  = r.y * (1.0f / G4_) - mean * mean;
    float inv  = rsqrtf(var + EPS_);

    const float* gxr = gx + ((long)b * SEQ_ + t) * G4_;
    float cval[2];
    float sc = 0.0f, ssc = 0.0f;
    #pragma unroll
    for (int rr = 0; rr < 2; rr++) {
        int j = rr * 256 + tid;
        float gi = (sg[j]        - mean) * inv * g_hh[j]        + b_hh[j]        + gxr[j];
        float gf = (sg[512 + j]  - mean) * inv * g_hh[512 + j]  + b_hh[512 + j]  + gxr[512 + j];
        float gg = (sg[1024 + j] - mean) * inv * g_hh[1024 + j] + b_hh[1024 + j] + gxr[1024 + j];
        float cn = sigm(gf) * c[(long)b * HID_ + j] + sigm(gi) * tanhf(gg);
        cval[rr] = cn;
        c[(long)b * HID_ + j] = cn;
        sc += cn; ssc += cn * cn;
    }
    float2 rc = blockReduce2(sc, ssc);
    float meanc = rc.x * (1.0f / HID_);
    float varc  = rc.y * (1.0f / HID_) - meanc * meanc;
    float invc  = rsqrtf(varc + EPS_);
    #pragma unroll
    for (int rr = 0; rr < 2; rr++) {
        int j = rr * 256 + tid;
        float go = (sg[1536 + j] - mean) * inv * g_hh[1536 + j] + b_hh[1536 + j] + gxr[1536 + j];
        float hn = sigm(go) * tanhf((cval[rr] - meanc) * invc * g_c[j] + b_c[j]);
        h[(long)b * HID_ + j] = hn;
        lstm[((long)b * SEQ_ + t) * HID_ + j] = hn;
    }
}

// Per (b,h): scores -> softmax -> m[b,h,:] = sum_s attn_s * lstm_out[b,s,:]
__global__ void __launch_bounds__(128)
attn_kernel(const float* __restrict__ kall, const float* __restrict__ qb,
            const float* __restrict__ lstm, float* __restrict__ mbuf)
{
    const int hidx = blockIdx.x;
    const int b    = blockIdx.y;
    const int tid  = threadIdx.x;
    __shared__ float ssc[SEQ_];
    __shared__ float wsum[SEQ_][4];

    float qv = qb[(long)b * DK_ + hidx * DH_ + tid];
    int w = tid >> 5, l = tid & 31;
    for (int s = 0; s < SEQ_; s++) {
        float v = kall[((long)b * SEQ_ + s) * DK_ + hidx * DH_ + tid] * qv;
        #pragma unroll
        for (int o = 16; o > 0; o >>= 1) v += __shfl_down_sync(0xffffffffu, v, o);
        if (l == 0) wsum[s][w] = v;
    }
    __syncthreads();
    if (tid < SEQ_) {
        float sc = wsum[tid][0] + wsum[tid][1] + wsum[tid][2] + wsum[tid][3];
        ssc[tid] = sc * 0.08838834764831845f;
    }
    __syncthreads();

    float e[SEQ_];
    float mx = -1e30f;
    #pragma unroll
    for (int s = 0; s < SEQ_; s++) mx = fmaxf(mx, ssc[s]);
    float den = 0.0f;
    #pragma unroll
    for (int s = 0; s < SEQ_; s++) { e[s] = expf(ssc[s] - mx); den += e[s]; }
    float dinv = 1.0f / den;

    #pragma unroll
    for (int rr = 0; rr < HID_ / 128; rr++) {
        int d = rr * 128 + tid;
        float acc = 0.0f;
        #pragma unroll
        for (int s = 0; s < SEQ_; s++)
            acc += e[s] * lstm[((long)b * SEQ_ + s) * HID_ + d];
        mbuf[((long)b * NH_ + hidx) * HID_ + d] = acc * dinv;
    }
}

__global__ void __launch_bounds__(256)
out_final_kernel(const float* __restrict__ oh, const float* __restrict__ outW,
                 const float* __restrict__ outb, const float* __restrict__ label,
                 float* __restrict__ out, float* __restrict__ diff)
{
    int w = threadIdx.x >> 5, l = threadIdx.x & 31;
    int b = blockIdx.x * 8 + w;
    float s = 0.0f;
    for (int j = l; j < DK_; j += 32) s += oh[(long)b * DK_ + j] * outW[j];
    #pragma unroll
    for (int o = 16; o > 0; o >>= 1) s += __shfl_down_sync(0xffffffffu, s, o);
    if (l == 0) {
        float v = s + outb[0];
        out[1 + b] = v;
        float d = v - label[(long)b * SEQ_ + (SEQ_ - 1)];
        diff[b] = d * d;
    }
}

__global__ void __launch_bounds__(256)
loss_kernel(const float* __restrict__ diff, float* __restrict__ out)
{
    float s = 0.0f;
    for (int j = threadIdx.x; j < B_; j += 256) s += diff[j];
    float2 r = blockReduce2(s, 0.0f);
    if (threadIdx.x == 0) out[0] = r.x * (1.0f / B_);
}

// ------------------------------- launch -------------------------------------
extern "C" void kernel_launch(void* const* d_in, const int* in_sizes, int n_in,
                              void* d_out, int out_size)
{
    const float* visual = (const float*)d_in[0];
    const float* text   = (const float*)d_in[1];
    const float* user   = (const float*)d_in[2];
    const float* cat    = (const float*)d_in[3];
    const float* label  = (const float*)d_in[4];
    const float* h0     = (const float*)d_in[5];
    const float* c0     = (const float*)d_in[6];
    const float* fus_W  = (const float*)d_in[7];
    const float* fus_b  = (const float*)d_in[8];
    const float* W_ih   = (const float*)d_in[9];
    const float* W_hh   = (const float*)d_in[10];
    const float* g_ih   = (const float*)d_in[11];
    const float* b_ih   = (const float*)d_in[12];
    const float* g_hh   = (const float*)d_in[13];
    const float* b_hh   = (const float*)d_in[14];
    const float* g_c    = (const float*)d_in[15];
    const float* b_c    = (const float*)d_in[16];
    const float* wq_W   = (const float*)d_in[17];
    const float* wq_b   = (const float*)d_in[18];
    const float* wk_W   = (const float*)d_in[19];
    const float* wk_b   = (const float*)d_in[20];
    const float* wv_W   = (const float*)d_in[21];
    const float* wv_b   = (const float*)d_in[22];
    const float* wout_W = (const float*)d_in[23];
    const float* wout_b = (const float*)d_in[24];
    const float* out_W  = (const float*)d_in[25];
    const float* out_b  = (const float*)d_in[26];
    float* out = (float*)d_out;

    float *vt, *gx, *hw, *h, *c, *lstm, *kall, *qb, *m, *ctx, *oh, *diff;
    cudaGetSymbolAddress((void**)&vt,   d_vt);
    cudaGetSymbolAddress((void**)&gx,   d_gx);
    cudaGetSymbolAddress((void**)&hw,   d_hw);
    cudaGetSymbolAddress((void**)&h,    d_h);
    cudaGetSymbolAddress((void**)&c,    d_c);
    cudaGetSymbolAddress((void**)&lstm, d_lstm);
    cudaGetSymbolAddress((void**)&kall, d_kall);
    cudaGetSymbolAddress((void**)&qb,   d_qb);
    cudaGetSymbolAddress((void**)&m,    d_m);
    cudaGetSymbolAddress((void**)&ctx,  d_ctx);
    cudaGetSymbolAddress((void**)&oh,   d_oh);
    cudaGetSymbolAddress((void**)&diff, d_diff);

    // 1. fused multimodal projection + relu: v_t (32768, 1024)
    tgemm_concat4<<<dim3(DIM_ / BN, BS_ / BM), 256>>>(
        visual, text, user, cat, fus_W, vt, fus_b);

    // 2. gx = v_t @ W_ih^T (32768, 2048), then LN
    tgemm_bt<<<dim3(G4_ / BN, BS_ / BM), 256>>>(
        vt, DIM_, 0, W_ih, DIM_, 0, gx, G4_, 0, DIM_, (const float*)0, 0, 0);
    ln_rows_kernel<<<BS_, 256>>>(gx, g_ih, b_ih);

    // 3. LSTM recurrence
    cudaMemcpyAsync(h, h0, (size_t)B_ * HID_ * sizeof(float), cudaMemcpyDeviceToDevice, 0);
    cudaMemcpyAsync(c, c0, (size_t)B_ * HID_ * sizeof(float), cudaMemcpyDeviceToDevice, 0);
    for (int t = 0; t < SEQ_; t++) {
        tgemm_bt<<<dim3(G4_ / BN, B_ / BM), 256>>>(
            h, HID_, 0, W_hh, HID_, 0, hw, G4_, 0, HID_, (const float*)0, 0, 0);
        lstm_cell_kernel<<<B_, 256>>>(hw, gx, g_hh, b_hh, g_c, b_c, h, c, lstm, t);
    }

    // 4. k / q projections
    tgemm_bt<<<dim3(DK_ / BN, BS_ / BM), 256>>>(
        lstm, HID_, 0, wk_W, HID_, 0, kall, DK_, 0, HID_, wk_b, 0, 0);
    tgemm_bt<<<dim3(DK_ / BN, B_ / BM), 256>>>(
        h, HID_, 0, wq_W, HID_, 0, qb, DK_, 0, HID_, wq_b, 0, 0);

    // 5. attention -> m (B,4,512)
    attn_kernel<<<dim3(NH_, B_), 128>>>(kall, qb, lstm, m);

    // 6. ctx (batched over heads)
    tgemm_bt<<<dim3(DK_ / BN, B_ / BM, NH_), 256>>>(
        m, NH_ * HID_, HID_, wv_W, HID_, (long)DK_ * HID_,
        ctx, NH_ * DK_, DK_, HID_, wv_b, DK_, 0);

    // 7. out_h = ctx @ wout_W^T + wout_b
    tgemm_bt<<<dim3(DK_ / BN, B_ / BM), 256>>>(
        ctx, NH_ * DK_, 0, wout_W, NH_ * DK_, 0, oh, DK_, 0, NH_ * DK_, wout_b, 0, 0);

    // 8. final projection + loss
    out_final_kernel<<<B_ / 8, 256>>>(oh, out_W, out_b, label, out, diff);
    loss_kernel<<<1, 256>>>(diff, out);
}